// round 7
// baseline (speedup 1.0000x reference)
#include <cuda_runtime.h>
#include <math.h>
#include <stdint.h>

// Problem constants
#define BATCH 2
#define SEQ   1024
#define TKN   2048      // BATCH*SEQ
#define HIDN  2048
#define NHEADS 32
#define KVN   512       // G*HD = 8*64
#define HD    64

// Scratch (static device arrays: no allocation allowed)
__device__ float g_Q[TKN * HIDN];
__device__ float g_K[TKN * KVN];
__device__ float g_V[TKN * KVN];
__device__ float g_A[TKN * HIDN];

// ---------------------------------------------------------------------------
// helpers
// ---------------------------------------------------------------------------
__device__ __forceinline__ uint32_t bf2(float lo, float hi) {
    uint32_t r;
    asm("cvt.rn.bf16x2.f32 %0, %1, %2;" : "=r"(r) : "f"(hi), "f"(lo));
    return r;
}

__device__ __forceinline__ uint32_t s2u(const void* p) {
    return (uint32_t)__cvta_generic_to_shared(p);
}

__device__ __forceinline__ void ldm_x4(uint32_t* r, uint32_t addr) {
    asm volatile("ldmatrix.sync.aligned.m8n8.x4.shared.b16 {%0,%1,%2,%3}, [%4];"
                 : "=r"(r[0]), "=r"(r[1]), "=r"(r[2]), "=r"(r[3]) : "r"(addr));
}
__device__ __forceinline__ void ldm_x4t(uint32_t* r, uint32_t addr) {
    asm volatile("ldmatrix.sync.aligned.m8n8.x4.trans.shared.b16 {%0,%1,%2,%3}, [%4];"
                 : "=r"(r[0]), "=r"(r[1]), "=r"(r[2]), "=r"(r[3]) : "r"(addr));
}

// mma.sync m16n8k16 bf16: D = A*B + D (fp32 accum)
__device__ __forceinline__ void mma16(float d[4], const uint32_t* a, const uint32_t* b) {
    asm volatile(
        "mma.sync.aligned.m16n8k16.row.col.f32.bf16.bf16.f32 "
        "{%0,%1,%2,%3}, {%4,%5,%6,%7}, {%8,%9}, {%0,%1,%2,%3};\n"
        : "+f"(d[0]), "+f"(d[1]), "+f"(d[2]), "+f"(d[3])
        : "r"(a[0]), "r"(a[1]), "r"(a[2]), "r"(a[3]), "r"(b[0]), "r"(b[1]));
}

// fast exp2 via FFMA polynomial (avoids MUFU throughput floor)
__device__ __forceinline__ float fast_exp2(float x) {
    x = fmaxf(x, -125.0f);
    int n = __float2int_rn(x);
    float f = x - (float)n;
    float p = 1.5403530393381609e-4f;
    p = fmaf(p, f, 1.3333558146428443e-3f);
    p = fmaf(p, f, 9.6181291076284772e-3f);
    p = fmaf(p, f, 5.5504108664821580e-2f);
    p = fmaf(p, f, 2.4022650695910071e-1f);
    p = fmaf(p, f, 6.9314718055994531e-1f);
    p = fmaf(p, f, 1.0f);
    return __int_as_float((n + 127) << 23) * p;
}

// ---------------------------------------------------------------------------
// bf16 GEMM core: 128x128 tile, k-chunk 32, double-buffered, ldmatrix frags.
// As rows 40 bf16 (80B): LDSM phases hit r*16 mod 128 -> 8 distinct groups.
// Bs rows 136 bf16 (272B): same property. 8 warps 2x4, warp 64x32.
// ---------------------------------------------------------------------------
#define AKU 20              // As row stride (u32) = 40 bf16 = 80 B
#define BNU 68              // Bs row stride (u32) = 136 bf16 = 272 B
#define ABUF (128 * AKU)    // u32 per As buffer (10240 B)
#define BBUF (32 * BNU)     // u32 per Bs buffer (8704 B)

__device__ __forceinline__ void gemm_core(
    const float* __restrict__ A, const float* __restrict__ B,
    const float* __restrict__ bias, float* __restrict__ C,
    const float* __restrict__ resid,
    int N, int K, int mb, int nb,
    uint32_t* AsU, uint32_t* BsU)
{
    const int tid = threadIdx.x, lane = tid & 31, warp = tid >> 5;
    const int wm = warp >> 2, wn = warp & 3;

    const float* Aptr = A + (size_t)(mb + (tid >> 1)) * K + (tid & 1) * 16;
    const float* Bptr = B + (size_t)(tid >> 3) * N + nb + (tid & 7) * 16;
    const int asb = (tid >> 1) * AKU + (tid & 1) * 8;
    const int bsb = (tid >> 3) * BNU + (tid & 7) * 8;

    float acc[4][4][4];
    #pragma unroll
    for (int i = 0; i < 4; i++)
        #pragma unroll
        for (int j = 0; j < 4; j++)
            #pragma unroll
            for (int q = 0; q < 4; q++) acc[i][j][q] = 0.0f;

    float4 ra[4], rb[4];
    #pragma unroll
    for (int i = 0; i < 4; i++) {
        ra[i] = *(const float4*)(Aptr + i * 4);
        rb[i] = *(const float4*)(Bptr + i * 4);
    }
    #pragma unroll
    for (int i = 0; i < 4; i++) {
        AsU[asb + 2 * i]     = bf2(ra[i].x, ra[i].y);
        AsU[asb + 2 * i + 1] = bf2(ra[i].z, ra[i].w);
        BsU[bsb + 2 * i]     = bf2(rb[i].x, rb[i].y);
        BsU[bsb + 2 * i + 1] = bf2(rb[i].z, rb[i].w);
    }
    __syncthreads();

    // ldmatrix base addresses (bytes)
    const uint32_t aBase = s2u(AsU) + (wm * 64 + (lane & 15)) * 80 + (lane >> 4) * 16;
    const uint32_t bBase = s2u(BsU) + (lane & 15) * 272 + (wn * 32 + (lane >> 4) * 8) * 2;

    const int nCh = K >> 5;
    for (int it = 0; it < nCh; it++) {
        const int cur = it & 1;
        if (it + 1 < nCh) {
            const float* ap = Aptr + (it + 1) * 32;
            const float* bp = Bptr + (size_t)(it + 1) * 32 * N;
            #pragma unroll
            for (int i = 0; i < 4; i++) {
                ra[i] = *(const float4*)(ap + i * 4);
                rb[i] = *(const float4*)(bp + i * 4);
            }
        }
        const uint32_t aB = aBase + cur * (ABUF * 4);
        const uint32_t bB = bBase + cur * (BBUF * 4);
        #pragma unroll
        for (int ks = 0; ks < 2; ks++) {
            uint32_t a[4][4], b[2][4];
            #pragma unroll
            for (int mt = 0; mt < 4; mt++)
                ldm_x4(a[mt], aB + mt * 16 * 80 + ks * 32);
            #pragma unroll
            for (int np = 0; np < 2; np++)
                ldm_x4t(b[np], bB + ks * 16 * 272 + np * 32);
            #pragma unroll
            for (int mt = 0; mt < 4; mt++)
                #pragma unroll
                for (int np = 0; np < 2; np++) {
                    mma16(acc[mt][2 * np],     a[mt], &b[np][0]);
                    mma16(acc[mt][2 * np + 1], a[mt], &b[np][2]);
                }
        }
        if (it + 1 < nCh) {
            const int nx = (it + 1) & 1;
            uint32_t* Ad = AsU + nx * ABUF;
            uint32_t* Bd = BsU + nx * BBUF;
            #pragma unroll
            for (int i = 0; i < 4; i++) {
                Ad[asb + 2 * i]     = bf2(ra[i].x, ra[i].y);
                Ad[asb + 2 * i + 1] = bf2(ra[i].z, ra[i].w);
                Bd[bsb + 2 * i]     = bf2(rb[i].x, rb[i].y);
                Bd[bsb + 2 * i + 1] = bf2(rb[i].z, rb[i].w);
            }
        }
        __syncthreads();
    }

    const int fr = lane >> 2, fc = lane & 3;
    const int r0 = mb + wm * 64 + fr;
    const int c0 = nb + wn * 32 + fc * 2;
    #pragma unroll
    for (int mt = 0; mt < 4; mt++) {
        #pragma unroll
        for (int nt = 0; nt < 4; nt++) {
            const int r = r0 + mt * 16;
            const int c = c0 + nt * 8;
            const float bx = bias[c], by = bias[c + 1];
            float2 v0 = make_float2(acc[mt][nt][0] + bx, acc[mt][nt][1] + by);
            float2 v1 = make_float2(acc[mt][nt][2] + bx, acc[mt][nt][3] + by);
            if (resid) {
                const float2 u0 = *(const float2*)&resid[(size_t)r * N + c];
                const float2 u1 = *(const float2*)&resid[(size_t)(r + 8) * N + c];
                v0.x += u0.x; v0.y += u0.y; v1.x += u1.x; v1.y += u1.y;
            }
            *(float2*)&C[(size_t)r * N + c]       = v0;
            *(float2*)&C[(size_t)(r + 8) * N + c] = v1;
        }
    }
}

// Fused Q/K/V projection: blockIdx.x [0,16)->Q, [16,20)->K, [20,24)->V.
__global__ __launch_bounds__(256) void qkv_gemm_kernel(
    const float* __restrict__ A,
    const float* __restrict__ Wq, const float* __restrict__ bq, float* __restrict__ Cq,
    const float* __restrict__ Wk, const float* __restrict__ bk, float* __restrict__ Ck,
    const float* __restrict__ Wv, const float* __restrict__ bv, float* __restrict__ Cv)
{
    __shared__ uint32_t AsU[2 * ABUF];
    __shared__ uint32_t BsU[2 * BBUF];
    const float* B; const float* bias; float* C; int N, nb;
    const int bx = blockIdx.x;
    if (bx < 16)      { B = Wq; bias = bq; C = Cq; N = HIDN; nb = bx * 128; }
    else if (bx < 20) { B = Wk; bias = bk; C = Ck; N = KVN;  nb = (bx - 16) * 128; }
    else              { B = Wv; bias = bv; C = Cv; N = KVN;  nb = (bx - 20) * 128; }
    gemm_core(A, B, bias, C, nullptr, N, HIDN, blockIdx.y * 128, nb, AsU, BsU);
}

// O projection with bias + residual.
__global__ __launch_bounds__(256) void gemm_o_kernel(
    const float* __restrict__ A,
    const float* __restrict__ B, const float* __restrict__ bias,
    float* __restrict__ C, const float* __restrict__ resid)
{
    __shared__ uint32_t AsU[2 * ABUF];
    __shared__ uint32_t BsU[2 * BBUF];
    gemm_core(A, B, bias, C, resid, HIDN, HIDN,
              blockIdx.y * 128, blockIdx.x * 128, AsU, BsU);
}

// ---------------------------------------------------------------------------
// Fused flash attention (bf16 mma + ldmatrix). block = (b,h,128 q rows).
// Qs/Ks rows 72 bf16 (144B), Vs rows 72 bf16 (144B), Ps rows 136 bf16 (272B).
// All LDSM-phase conflict-free (row*16 mod 128 distinct). 2 CTAs/SM.
// ---------------------------------------------------------------------------
#define FQ_STR 36
#define FP_STR 68
#define FV_STR 72

#define FA_QS   0
#define FA_KS   (128 * FQ_STR)               // 4608
#define FA_VS   (2 * 128 * FQ_STR)           // 9216
#define FA_PS   (FA_VS + 128 * FV_STR / 2)   // 13824
#define FA_RED  (FA_PS + 128 * FP_STR)       // 22528
#define FA_SUM  (FA_RED + 512)
#define FA_RM   (FA_SUM + 512)
#define FA_RL   (FA_RM + 128)
#define FA_AB   (FA_RL + 128)
#define FA_U32S (FA_AB + 128)                // 23936
#define FA_SMEM (FA_U32S * 4)                // 95744 B

__global__ __launch_bounds__(256, 2) void fa_kernel(
    const float* __restrict__ Q, const float* __restrict__ K,
    const float* __restrict__ V, const float* __restrict__ mask,
    float* __restrict__ Aout)
{
    extern __shared__ uint32_t shu[];
    uint32_t* Qs = shu + FA_QS;
    uint32_t* Ks = shu + FA_KS;
    unsigned short* Vs = (unsigned short*)(shu + FA_VS);
    uint32_t* Ps = shu + FA_PS;
    float* red = (float*)(shu + FA_RED);
    float* sb  = (float*)(shu + FA_SUM);
    float* rm  = (float*)(shu + FA_RM);
    float* rl  = (float*)(shu + FA_RL);
    float* ab  = (float*)(shu + FA_AB);

    const int tid = threadIdx.x, lane = tid & 31, warp = tid >> 5;
    const int z = blockIdx.y, b = z >> 5, h = z & 31, g = h >> 2;
    const int q0 = blockIdx.x * 128;
    const size_t tb = (size_t)b * SEQ;
    const float* mbase = mask + (size_t)b * SEQ * SEQ;

    const int wm = warp >> 2, wn = warp & 3;
    const int fr = lane >> 2, fc = lane & 3;

    // ldmatrix base addresses (bytes)
    const uint32_t qA = s2u(Qs) + (wm * 64 + (lane & 15)) * 144 + (lane >> 4) * 16;
    const uint32_t kA = s2u(Ks) + (wn * 32 + (lane & 7) + (lane >> 4) * 8) * 144
                                + ((lane >> 3) & 1) * 16;
    const uint32_t pA = s2u(Ps) + (warp * 16 + (lane & 15)) * 272 + (lane >> 4) * 16;
    const uint32_t vA = s2u(Vs) + ((lane & 7) + ((lane >> 3) & 1) * 8) * 144
                                + (lane >> 4) * 16;

    // load Q tile, prescale by (1/8)*log2(e), pack bf16
    const float qsc = 0.125f * 1.4426950408889634f;
    {
        const int r = tid >> 4, c = (tid & 15) * 4;
        #pragma unroll
        for (int p = 0; p < 8; p++) {
            const int row = r + p * 16;
            float4 v = *(const float4*)&Q[(tb + q0 + row) * HIDN + h * 64 + c];
            Qs[row * FQ_STR + (c >> 1)]     = bf2(v.x * qsc, v.y * qsc);
            Qs[row * FQ_STR + (c >> 1) + 1] = bf2(v.z * qsc, v.w * qsc);
        }
    }
    if (tid < 128) { rm[tid] = -1e30f; rl[tid] = 0.0f; }

    float acc_o[8][4];
    #pragma unroll
    for (int i = 0; i < 8; i++)
        #pragma unroll
        for (int q = 0; q < 4; q++) acc_o[i][q] = 0.0f;

    for (int t = 0; t < 8; t++) {
        __syncthreads();  // prev PV done with Ks/Vs; first iter: Qs/rm ready
        {
            const int r = tid >> 4, c = (tid & 15) * 4;
            #pragma unroll
            for (int p = 0; p < 8; p++) {
                const int row = r + p * 16;
                const size_t goff = (tb + t * 128 + row) * KVN + g * 64 + c;
                float4 kw = *(const float4*)&K[goff];
                float4 vw = *(const float4*)&V[goff];
                Ks[row * FQ_STR + (c >> 1)]     = bf2(kw.x, kw.y);
                Ks[row * FQ_STR + (c >> 1) + 1] = bf2(kw.z, kw.w);
                *(uint32_t*)&Vs[row * FV_STR + c]     = bf2(vw.x, vw.y);
                *(uint32_t*)&Vs[row * FV_STR + c + 2] = bf2(vw.z, vw.w);
            }
        }
        __syncthreads();

        // ---- S = Qs @ Ks^T (warp 64x32), 4 k16 steps over d=64 ----
        float s[4][4][4];
        #pragma unroll
        for (int i = 0; i < 4; i++)
            #pragma unroll
            for (int j = 0; j < 4; j++)
                #pragma unroll
                for (int q = 0; q < 4; q++) s[i][j][q] = 0.0f;

        #pragma unroll
        for (int ks = 0; ks < 4; ks++) {
            uint32_t a[4][4], bq_[2][4];
            #pragma unroll
            for (int mt = 0; mt < 4; mt++)
                ldm_x4(a[mt], qA + mt * 16 * 144 + ks * 32);
            #pragma unroll
            for (int np = 0; np < 2; np++)
                ldm_x4(bq_[np], kA + np * 16 * 144 + ks * 32);
            #pragma unroll
            for (int mt = 0; mt < 4; mt++)
                #pragma unroll
                for (int np = 0; np < 2; np++) {
                    mma16(s[mt][2 * np],     a[mt], &bq_[np][0]);
                    mma16(s[mt][2 * np + 1], a[mt], &bq_[np][2]);
                }
        }

        // ---- mask multiply + per-row tile max ----
        #pragma unroll
        for (int mt = 0; mt < 4; mt++) {
            const int r0 = wm * 64 + mt * 16 + fr;
            float m0 = -1e30f, m1 = -1e30f;
            #pragma unroll
            for (int nt = 0; nt < 4; nt++) {
                const int cg = t * 128 + wn * 32 + nt * 8 + 2 * fc;
                const float2 k0 = *(const float2*)&mbase[(size_t)(q0 + r0) * SEQ + cg];
                const float2 k1 = *(const float2*)&mbase[(size_t)(q0 + r0 + 8) * SEQ + cg];
                s[mt][nt][0] *= k0.x; s[mt][nt][1] *= k0.y;
                s[mt][nt][2] *= k1.x; s[mt][nt][3] *= k1.y;
                m0 = fmaxf(m0, fmaxf(s[mt][nt][0], s[mt][nt][1]));
                m1 = fmaxf(m1, fmaxf(s[mt][nt][2], s[mt][nt][3]));
            }
            m0 = fmaxf(m0, __shfl_xor_sync(0xffffffffu, m0, 1));
            m0 = fmaxf(m0, __shfl_xor_sync(0xffffffffu, m0, 2));
            m1 = fmaxf(m1, __shfl_xor_sync(0xffffffffu, m1, 1));
            m1 = fmaxf(m1, __shfl_xor_sync(0xffffffffu, m1, 2));
            if (fc == 0) {
                red[wn * 128 + r0]     = m0;
                red[wn * 128 + r0 + 8] = m1;
            }
        }
        __syncthreads();

        // ---- p = exp2(s - m_new), stage P (bf16 pairs), partial sums ----
        #pragma unroll
        for (int mt = 0; mt < 4; mt++) {
            const int r0 = wm * 64 + mt * 16 + fr;
            const int r1 = r0 + 8;
            float mn0 = fmaxf(fmaxf(red[r0], red[128 + r0]),
                              fmaxf(red[256 + r0], red[384 + r0]));
            float mn1 = fmaxf(fmaxf(red[r1], red[128 + r1]),
                              fmaxf(red[256 + r1], red[384 + r1]));
            mn0 = fmaxf(mn0, rm[r0]);
            mn1 = fmaxf(mn1, rm[r1]);
            float s0 = 0.0f, s1 = 0.0f;
            #pragma unroll
            for (int nt = 0; nt < 4; nt++) {
                const float p0 = fast_exp2(s[mt][nt][0] - mn0);
                const float p1 = fast_exp2(s[mt][nt][1] - mn0);
                const float p2 = fast_exp2(s[mt][nt][2] - mn1);
                const float p3 = fast_exp2(s[mt][nt][3] - mn1);
                s0 += p0 + p1; s1 += p2 + p3;
                const int cw = wn * 16 + nt * 4 + fc;
                Ps[r0 * FP_STR + cw] = bf2(p0, p1);
                Ps[r1 * FP_STR + cw] = bf2(p2, p3);
            }
            s0 += __shfl_xor_sync(0xffffffffu, s0, 1);
            s0 += __shfl_xor_sync(0xffffffffu, s0, 2);
            s1 += __shfl_xor_sync(0xffffffffu, s1, 1);
            s1 += __shfl_xor_sync(0xffffffffu, s1, 2);
            if (fc == 0) {
                sb[wn * 128 + r0] = s0;
                sb[wn * 128 + r1] = s1;
            }
        }
        __syncthreads();

        // ---- per-row running state update ----
        if (tid < 128) {
            const float mo = rm[tid];
            float tm = fmaxf(fmaxf(red[tid], red[128 + tid]),
                             fmaxf(red[256 + tid], red[384 + tid]));
            const float mn = fmaxf(mo, tm);
            const float al = fast_exp2(mo - mn);
            const float ts = sb[tid] + sb[128 + tid] + sb[256 + tid] + sb[384 + tid];
            rl[tid] = rl[tid] * al + ts;
            rm[tid] = mn;
            ab[tid] = al;
        }
        __syncthreads();

        // ---- PV: acc_o = acc_o*alpha + P @ V, 8 k16 steps over 128 keys ----
        {
            const int r0 = warp * 16 + fr;
            const float al0 = ab[r0], al1 = ab[r0 + 8];
            #pragma unroll
            for (int nt = 0; nt < 8; nt++) {
                acc_o[nt][0] *= al0; acc_o[nt][1] *= al0;
                acc_o[nt][2] *= al1; acc_o[nt][3] *= al1;
            }
            #pragma unroll
            for (int ks = 0; ks < 8; ks++) {
                uint32_t a[4];
                ldm_x4(a, pA + ks * 32);
                #pragma unroll
                for (int np = 0; np < 4; np++) {
                    uint32_t bv_[4];
                    ldm_x4t(bv_, vA + ks * 16 * 144 + np * 32);
                    mma16(acc_o[2 * np],     a, &bv_[0]);
                    mma16(acc_o[2 * np + 1], a, &bv_[2]);
                }
            }
        }
    }

    // ---- normalize and write ----
    {
        const int r0 = warp * 16 + fr;
        const float i0 = 1.0f / rl[r0];
        const float i1 = 1.0f / rl[r0 + 8];
        #pragma unroll
        for (int nt = 0; nt < 8; nt++) {
            const int c = nt * 8 + 2 * fc;
            *(float2*)&Aout[(tb + q0 + r0) * HIDN + h * 64 + c] =
                make_float2(acc_o[nt][0] * i0, acc_o[nt][1] * i0);
            *(float2*)&Aout[(tb + q0 + r0 + 8) * HIDN + h * 64 + c] =
                make_float2(acc_o[nt][2] * i1, acc_o[nt][3] * i1);
        }
    }
}

// ---------------------------------------------------------------------------
// launch
// ---------------------------------------------------------------------------
extern "C" void kernel_launch(void* const* d_in, const int* in_sizes, int n_in,
                              void* d_out, int out_size)
{
    (void)in_sizes; (void)n_in; (void)out_size;
    const float* x    = (const float*)d_in[0];
    const float* mask = (const float*)d_in[1];
    const float* Wq   = (const float*)d_in[2];
    const float* bq   = (const float*)d_in[3];
    const float* Wk   = (const float*)d_in[4];
    const float* bk   = (const float*)d_in[5];
    const float* Wv   = (const float*)d_in[6];
    const float* bv   = (const float*)d_in[7];
    const float* Wo   = (const float*)d_in[8];
    const float* bo   = (const float*)d_in[9];
    float* out = (float*)d_out;

    float *Qp, *Kp, *Vp, *Ap;
    cudaGetSymbolAddress((void**)&Qp, g_Q);
    cudaGetSymbolAddress((void**)&Kp, g_K);
    cudaGetSymbolAddress((void**)&Vp, g_V);
    cudaGetSymbolAddress((void**)&Ap, g_A);

    cudaFuncSetAttribute(fa_kernel, cudaFuncAttributeMaxDynamicSharedMemorySize, FA_SMEM);

    // fused Q/K/V projections
    qkv_gemm_kernel<<<dim3(24, 16), 256>>>(x, Wq, bq, Qp, Wk, bk, Kp, Wv, bv, Vp);
    // fused attention
    fa_kernel<<<dim3(8, 64), 256, FA_SMEM>>>(Qp, Kp, Vp, mask, Ap);
    // output projection + bias + residual
    gemm_o_kernel<<<dim3(16, 16), 256>>>(Ap, Wo, bo, out, x);
}

// round 13
// speedup vs baseline: 1.1700x; 1.1700x over previous
#include <cuda_runtime.h>
#include <cuda_bf16.h>
#include <math.h>
#include <stdint.h>

// Problem constants
#define BATCH 2
#define SEQ   1024
#define TKN   2048      // BATCH*SEQ
#define HIDN  2048
#define NHEADS 32
#define KVN   512       // G*HD = 8*64
#define HD    64

// Scratch (static device arrays: no allocation allowed)
__device__ __nv_bfloat16 g_xb [TKN * HIDN];
__device__ __nv_bfloat16 g_WqT[HIDN * HIDN];
__device__ __nv_bfloat16 g_WkT[KVN * HIDN];
__device__ __nv_bfloat16 g_WvT[KVN * HIDN];
__device__ __nv_bfloat16 g_WoT[HIDN * HIDN];
__device__ __nv_bfloat16 g_Qb [TKN * HIDN];
__device__ __nv_bfloat16 g_Kb [TKN * KVN];
__device__ __nv_bfloat16 g_Vb [TKN * KVN];
__device__ __nv_bfloat16 g_Ab [TKN * HIDN];

// ---------------------------------------------------------------------------
// helpers
// ---------------------------------------------------------------------------
__device__ __forceinline__ uint32_t bf2(float lo, float hi) {
    uint32_t r;
    asm("cvt.rn.bf16x2.f32 %0, %1, %2;" : "=r"(r) : "f"(hi), "f"(lo));
    return r;
}
__device__ __forceinline__ float2 ubf2(uint32_t w) {
    __nv_bfloat162 h = *reinterpret_cast<__nv_bfloat162*>(&w);
    return __bfloat1622float2(h);
}
__device__ __forceinline__ uint32_t s2u(const void* p) {
    return (uint32_t)__cvta_generic_to_shared(p);
}

// mma.sync m16n8k16 bf16: D = A*B + D (fp32 accum)
__device__ __forceinline__ void mma16(float d[4], const uint32_t* a, const uint32_t* b) {
    asm volatile(
        "mma.sync.aligned.m16n8k16.row.col.f32.bf16.bf16.f32 "
        "{%0,%1,%2,%3}, {%4,%5,%6,%7}, {%8,%9}, {%0,%1,%2,%3};\n"
        : "+f"(d[0]), "+f"(d[1]), "+f"(d[2]), "+f"(d[3])
        : "r"(a[0]), "r"(a[1]), "r"(a[2]), "r"(a[3]), "r"(b[0]), "r"(b[1]));
}

__device__ __forceinline__ float fast_exp2(float x) {
    x = fmaxf(x, -125.0f);
    int n = __float2int_rn(x);
    float f = x - (float)n;
    float p = 1.5403530393381609e-4f;
    p = fmaf(p, f, 1.3333558146428443e-3f);
    p = fmaf(p, f, 9.6181291076284772e-3f);
    p = fmaf(p, f, 5.5504108664821580e-2f);
    p = fmaf(p, f, 2.4022650695910071e-1f);
    p = fmaf(p, f, 6.9314718055994531e-1f);
    p = fmaf(p, f, 1.0f);
    return __int_as_float((n + 127) << 23) * p;
}

__device__ __forceinline__ void cpa16(uint32_t dst, const void* src) {
    asm volatile("cp.async.cg.shared.global [%0], [%1], 16;\n" :: "r"(dst), "l"(src));
}

// ---------------------------------------------------------------------------
// Prep kernels: x fp32 -> bf16; W[K,N] fp32 -> WT[N,K] bf16
// ---------------------------------------------------------------------------
__global__ __launch_bounds__(256) void cvt_x_kernel(const float* __restrict__ x,
                                                    __nv_bfloat16* __restrict__ xb)
{
    const size_t i = ((size_t)blockIdx.x * 256 + threadIdx.x) * 8;
    float4 a = *(const float4*)&x[i];
    float4 b = *(const float4*)&x[i + 4];
    uint4 o;
    o.x = bf2(a.x, a.y); o.y = bf2(a.z, a.w);
    o.z = bf2(b.x, b.y); o.w = bf2(b.z, b.w);
    *(uint4*)&xb[i] = o;
}

__global__ __launch_bounds__(256) void transpose_w_kernel(
    const float* __restrict__ W, __nv_bfloat16* __restrict__ WT, int K, int N)
{
    __shared__ unsigned short t[64][66];
    const int n0 = blockIdx.x * 64, k0 = blockIdx.y * 64;
    const int r = threadIdx.x >> 4, c4 = (threadIdx.x & 15) * 4;
    #pragma unroll
    for (int j = 0; j < 4; j++) {
        const int kk = r + j * 16;
        float4 v = *(const float4*)&W[(size_t)(k0 + kk) * N + n0 + c4];
        uint32_t p0 = bf2(v.x, v.y), p1 = bf2(v.z, v.w);
        t[kk][c4]     = (unsigned short)(p0 & 0xFFFF);
        t[kk][c4 + 1] = (unsigned short)(p0 >> 16);
        t[kk][c4 + 2] = (unsigned short)(p1 & 0xFFFF);
        t[kk][c4 + 3] = (unsigned short)(p1 >> 16);
    }
    __syncthreads();
    #pragma unroll
    for (int j = 0; j < 4; j++) {
        const int nn = r + j * 16;
        uint32_t u0 = (uint32_t)t[c4][nn]     | ((uint32_t)t[c4 + 1][nn] << 16);
        uint32_t u1 = (uint32_t)t[c4 + 2][nn] | ((uint32_t)t[c4 + 3][nn] << 16);
        *(uint2*)&WT[(size_t)(n0 + nn) * K + k0 + c4] = make_uint2(u0, u1);
    }
}

// ---------------------------------------------------------------------------
// NT bf16 GEMM core: C[128,128] = A[M,2048] @ WT[N,2048]^T (+bias, +resid).
// k-chunk 64 (32 u32/row, stride 36: proven conflict-free gathers),
// cp.async double-buffered, 8 warps 2x4, warp 64x32, 2 CTAs/SM.
// ---------------------------------------------------------------------------
#define GSTR 36               // u32 row stride (32 data + 4 pad) = 144 B
#define GBUF (128 * GSTR)     // u32 per operand buffer (18432 B)
#define G_SMEM (4 * GBUF * 4) // 73728 B

template <bool OUT_BF16>
__device__ __forceinline__ void gemm_nt_core(
    const __nv_bfloat16* __restrict__ Ag, const __nv_bfloat16* __restrict__ Bt,
    const float* __restrict__ bias, void* __restrict__ Cout,
    const float* __restrict__ resid, int Ncols, int mb, int nb)
{
    extern __shared__ __align__(16) uint32_t sh[];
    uint32_t* As = sh;               // [2][GBUF]
    uint32_t* Bs = sh + 2 * GBUF;    // [2][GBUF]

    const int tid = threadIdx.x, lane = tid & 31, warp = tid >> 5;
    const int wm = warp >> 2, wn = warp & 3;
    const int fr = lane >> 2, fc = lane & 3;

    // loader mapping: 2 threads per row, 4x16B lines each
    const int lrow = tid >> 1, lhalf = (tid & 1) * 64;   // byte offset in row
    const uint32_t aDst = s2u(As) + lrow * 144 + lhalf;
    const uint32_t bDst = s2u(Bs) + lrow * 144 + lhalf;
    const __nv_bfloat16* aSrc = Ag + (size_t)(mb + lrow) * HIDN + lhalf / 2;
    const __nv_bfloat16* bSrc = Bt + (size_t)(nb + lrow) * HIDN + lhalf / 2;

    float acc[4][4][4];
    #pragma unroll
    for (int i = 0; i < 4; i++)
        #pragma unroll
        for (int j = 0; j < 4; j++)
            #pragma unroll
            for (int q = 0; q < 4; q++) acc[i][j][q] = 0.0f;

    // prologue: chunk 0
    {
        #pragma unroll
        for (int l = 0; l < 4; l++) {
            cpa16(aDst + l * 16, aSrc + l * 8);
            cpa16(bDst + l * 16, bSrc + l * 8);
        }
        asm volatile("cp.async.commit_group;\n");
    }

    const int nCh = HIDN / 64;   // 32
    for (int it = 0; it < nCh; it++) {
        if (it + 1 < nCh) {
            const int buf = (it + 1) & 1;
            const uint32_t aB = aDst + buf * (GBUF * 4);
            const uint32_t bB = bDst + buf * (GBUF * 4);
            const __nv_bfloat16* as = aSrc + (it + 1) * 64;
            const __nv_bfloat16* bs = bSrc + (it + 1) * 64;
            #pragma unroll
            for (int l = 0; l < 4; l++) {
                cpa16(aB + l * 16, as + l * 8);
                cpa16(bB + l * 16, bs + l * 8);
            }
            asm volatile("cp.async.commit_group;\n");
            asm volatile("cp.async.wait_group 1;\n");
        } else {
            asm volatile("cp.async.wait_group 0;\n");
        }
        __syncthreads();

        const int base = (it & 1) * GBUF;
        #pragma unroll
        for (int ks = 0; ks < 4; ks++) {
            const int kb = ks * 8 + fc;
            uint32_t a[4][4], b[4][2];
            #pragma unroll
            for (int mt = 0; mt < 4; mt++) {
                const int row = base + (wm * 64 + mt * 16 + fr) * GSTR;
                a[mt][0] = As[row + kb];
                a[mt][1] = As[row + 8 * GSTR + kb];
                a[mt][2] = As[row + kb + 4];
                a[mt][3] = As[row + 8 * GSTR + kb + 4];
            }
            #pragma unroll
            for (int nt = 0; nt < 4; nt++) {
                const int row = base + (wn * 32 + nt * 8 + fr) * GSTR;
                b[nt][0] = Bs[row + kb];
                b[nt][1] = Bs[row + kb + 4];
            }
            #pragma unroll
            for (int mt = 0; mt < 4; mt++)
                #pragma unroll
                for (int nt = 0; nt < 4; nt++)
                    mma16(acc[mt][nt], a[mt], b[nt]);
        }
        __syncthreads();
    }

    // epilogue
    const int r0 = mb + wm * 64 + fr;
    const int c0 = nb + wn * 32 + fc * 2;
    #pragma unroll
    for (int mt = 0; mt < 4; mt++) {
        #pragma unroll
        for (int nt = 0; nt < 4; nt++) {
            const int r = r0 + mt * 16;
            const int c = c0 + nt * 8;
            const float bx = bias[c], by = bias[c + 1];
            if (OUT_BF16) {
                __nv_bfloat16* C = (__nv_bfloat16*)Cout;
                *(uint32_t*)&C[(size_t)r * Ncols + c] =
                    bf2(acc[mt][nt][0] + bx, acc[mt][nt][1] + by);
                *(uint32_t*)&C[(size_t)(r + 8) * Ncols + c] =
                    bf2(acc[mt][nt][2] + bx, acc[mt][nt][3] + by);
            } else {
                float* C = (float*)Cout;
                const float2 u0 = *(const float2*)&resid[(size_t)r * Ncols + c];
                const float2 u1 = *(const float2*)&resid[(size_t)(r + 8) * Ncols + c];
                *(float2*)&C[(size_t)r * Ncols + c] =
                    make_float2(acc[mt][nt][0] + bx + u0.x, acc[mt][nt][1] + by + u0.y);
                *(float2*)&C[(size_t)(r + 8) * Ncols + c] =
                    make_float2(acc[mt][nt][2] + bx + u1.x, acc[mt][nt][3] + by + u1.y);
            }
        }
    }
}

// Fused Q/K/V projection: blockIdx.x [0,16)->Q, [16,20)->K, [20,24)->V.
__global__ __launch_bounds__(256, 2) void qkv_gemm_kernel(
    const __nv_bfloat16* __restrict__ xb,
    const __nv_bfloat16* __restrict__ WqT, const float* __restrict__ bq, __nv_bfloat16* __restrict__ Qb,
    const __nv_bfloat16* __restrict__ WkT, const float* __restrict__ bk, __nv_bfloat16* __restrict__ Kb,
    const __nv_bfloat16* __restrict__ WvT, const float* __restrict__ bv, __nv_bfloat16* __restrict__ Vb)
{
    const int bx = blockIdx.x, mrow = blockIdx.y * 128;
    if (bx < 16)
        gemm_nt_core<true>(xb, WqT, bq, Qb, nullptr, HIDN, mrow, bx * 128);
    else if (bx < 20)
        gemm_nt_core<true>(xb, WkT, bk, Kb, nullptr, KVN, mrow, (bx - 16) * 128);
    else
        gemm_nt_core<true>(xb, WvT, bv, Vb, nullptr, KVN, mrow, (bx - 20) * 128);
}

// O projection: fp32 out + bias + residual.
__global__ __launch_bounds__(256, 2) void o_gemm_kernel(
    const __nv_bfloat16* __restrict__ Ab, const __nv_bfloat16* __restrict__ WoT,
    const float* __restrict__ bo, float* __restrict__ out,
    const float* __restrict__ resid)
{
    gemm_nt_core<false>(Ab, WoT, bo, out, resid, HIDN,
                        blockIdx.y * 128, blockIdx.x * 128);
}

// ---------------------------------------------------------------------------
// Fused flash attention (R4 proven config; bf16 in/out).
// block = (b,h,128 q rows), 8 k-tiles of 128 keys, 2 CTAs/SM.
// ---------------------------------------------------------------------------
#define FQ_STR 36
#define FP_STR 68
#define FV_STR 72

#define FA_QS   0
#define FA_KS   (128 * FQ_STR)
#define FA_VS   (2 * 128 * FQ_STR)
#define FA_PS   (FA_VS + 128 * FV_STR / 2)
#define FA_RED  (FA_PS + 128 * FP_STR)
#define FA_SUM  (FA_RED + 512)
#define FA_RM   (FA_SUM + 512)
#define FA_RL   (FA_RM + 128)
#define FA_AB   (FA_RL + 128)
#define FA_U32S (FA_AB + 128)
#define FA_SMEM (FA_U32S * 4)

__global__ __launch_bounds__(256, 2) void fa_kernel(
    const __nv_bfloat16* __restrict__ Q, const __nv_bfloat16* __restrict__ K,
    const __nv_bfloat16* __restrict__ V, const float* __restrict__ mask,
    __nv_bfloat16* __restrict__ Aout)
{
    extern __shared__ uint32_t shu[];
    uint32_t* Qs = shu + FA_QS;
    uint32_t* Ks = shu + FA_KS;
    unsigned short* Vs = (unsigned short*)(shu + FA_VS);
    uint32_t* Ps = shu + FA_PS;
    float* red = (float*)(shu + FA_RED);
    float* sb  = (float*)(shu + FA_SUM);
    float* rm  = (float*)(shu + FA_RM);
    float* rl  = (float*)(shu + FA_RL);
    float* ab  = (float*)(shu + FA_AB);

    const int tid = threadIdx.x, lane = tid & 31, warp = tid >> 5;
    const int z = blockIdx.y, b = z >> 5, h = z & 31, g = h >> 2;
    const int q0 = blockIdx.x * 128;
    const size_t tb = (size_t)b * SEQ;
    const float* mbase = mask + (size_t)b * SEQ * SEQ;

    const int wm = warp >> 2, wn = warp & 3;
    const int fr = lane >> 2, fc = lane & 3;

    // load Q tile (bf16), prescale by (1/8)*log2(e)
    const float qsc = 0.125f * 1.4426950408889634f;
    {
        const int r = tid >> 4, c = (tid & 15) * 4;
        const uint32_t* qp = (const uint32_t*)Q;
        #pragma unroll
        for (int p = 0; p < 8; p++) {
            const int row = r + p * 16;
            const size_t w = ((tb + q0 + row) * HIDN + h * 64 + c) >> 1;
            float2 f0 = ubf2(qp[w]), f1 = ubf2(qp[w + 1]);
            Qs[row * FQ_STR + (c >> 1)]     = bf2(f0.x * qsc, f0.y * qsc);
            Qs[row * FQ_STR + (c >> 1) + 1] = bf2(f1.x * qsc, f1.y * qsc);
        }
    }
    if (tid < 128) { rm[tid] = -1e30f; rl[tid] = 0.0f; }

    float acc_o[8][4];
    #pragma unroll
    for (int i = 0; i < 8; i++)
        #pragma unroll
        for (int q = 0; q < 4; q++) acc_o[i][q] = 0.0f;

    for (int t = 0; t < 8; t++) {
        __syncthreads();
        {
            const int r = tid >> 4, c = (tid & 15) * 4;
            const uint32_t* kp = (const uint32_t*)K;
            const uint32_t* vp = (const uint32_t*)V;
            #pragma unroll
            for (int p = 0; p < 8; p++) {
                const int row = r + p * 16;
                const size_t w = ((tb + t * 128 + row) * KVN + g * 64 + c) >> 1;
                Ks[row * FQ_STR + (c >> 1)]     = kp[w];
                Ks[row * FQ_STR + (c >> 1) + 1] = kp[w + 1];
                *(uint32_t*)&Vs[row * FV_STR + c]     = vp[w];
                *(uint32_t*)&Vs[row * FV_STR + c + 2] = vp[w + 1];
            }
        }
        __syncthreads();

        // ---- S = Qs @ Ks^T (warp 64x32) ----
        float s[4][4][4];
        #pragma unroll
        for (int i = 0; i < 4; i++)
            #pragma unroll
            for (int j = 0; j < 4; j++)
                #pragma unroll
                for (int q = 0; q < 4; q++) s[i][j][q] = 0.0f;

        #pragma unroll
        for (int ks = 0; ks < 4; ks++) {
            const int kb = ks * 8 + fc;
            uint32_t a[4][4], bq_[4][2];
            #pragma unroll
            for (int mt = 0; mt < 4; mt++) {
                const int row = (wm * 64 + mt * 16 + fr) * FQ_STR;
                a[mt][0] = Qs[row + kb];
                a[mt][1] = Qs[row + 8 * FQ_STR + kb];
                a[mt][2] = Qs[row + kb + 4];
                a[mt][3] = Qs[row + 8 * FQ_STR + kb + 4];
            }
            #pragma unroll
            for (int nt = 0; nt < 4; nt++) {
                const int row = (wn * 32 + nt * 8 + fr) * FQ_STR;
                bq_[nt][0] = Ks[row + kb];
                bq_[nt][1] = Ks[row + kb + 4];
            }
            #pragma unroll
            for (int mt = 0; mt < 4; mt++)
                #pragma unroll
                for (int nt = 0; nt < 4; nt++)
                    mma16(s[mt][nt], a[mt], bq_[nt]);
        }

        // ---- mask multiply + per-row tile max ----
        #pragma unroll
        for (int mt = 0; mt < 4; mt++) {
            const int r0 = wm * 64 + mt * 16 + fr;
            float m0 = -1e30f, m1 = -1e30f;
            #pragma unroll
            for (int nt = 0; nt < 4; nt++) {
                const int cg = t * 128 + wn * 32 + nt * 8 + 2 * fc;
                const float2 k0 = *(const float2*)&mbase[(size_t)(q0 + r0) * SEQ + cg];
                const float2 k1 = *(const float2*)&mbase[(size_t)(q0 + r0 + 8) * SEQ + cg];
                s[mt][nt][0] *= k0.x; s[mt][nt][1] *= k0.y;
                s[mt][nt][2] *= k1.x; s[mt][nt][3] *= k1.y;
                m0 = fmaxf(m0, fmaxf(s[mt][nt][0], s[mt][nt][1]));
                m1 = fmaxf(m1, fmaxf(s[mt][nt][2], s[mt][nt][3]));
            }
            m0 = fmaxf(m0, __shfl_xor_sync(0xffffffffu, m0, 1));
            m0 = fmaxf(m0, __shfl_xor_sync(0xffffffffu, m0, 2));
            m1 = fmaxf(m1, __shfl_xor_sync(0xffffffffu, m1, 1));
            m1 = fmaxf(m1, __shfl_xor_sync(0xffffffffu, m1, 2));
            if (fc == 0) {
                red[wn * 128 + r0]     = m0;
                red[wn * 128 + r0 + 8] = m1;
            }
        }
        __syncthreads();

        // ---- p = exp2(s - m_new), stage P (bf16), partial sums ----
        #pragma unroll
        for (int mt = 0; mt < 4; mt++) {
            const int r0 = wm * 64 + mt * 16 + fr;
            const int r1 = r0 + 8;
            float mn0 = fmaxf(fmaxf(red[r0], red[128 + r0]),
                              fmaxf(red[256 + r0], red[384 + r0]));
            float mn1 = fmaxf(fmaxf(red[r1], red[128 + r1]),
                              fmaxf(red[256 + r1], red[384 + r1]));
            mn0 = fmaxf(mn0, rm[r0]);
            mn1 = fmaxf(mn1, rm[r1]);
            float s0 = 0.0f, s1 = 0.0f;
            #pragma unroll
            for (int nt = 0; nt < 4; nt++) {
                const float p0 = fast_exp2(s[mt][nt][0] - mn0);
                const float p1 = fast_exp2(s[mt][nt][1] - mn0);
                const float p2 = fast_exp2(s[mt][nt][2] - mn1);
                const float p3 = fast_exp2(s[mt][nt][3] - mn1);
                s0 += p0 + p1; s1 += p2 + p3;
                const int cw = wn * 16 + nt * 4 + fc;
                Ps[r0 * FP_STR + cw] = bf2(p0, p1);
                Ps[r1 * FP_STR + cw] = bf2(p2, p3);
            }
            s0 += __shfl_xor_sync(0xffffffffu, s0, 1);
            s0 += __shfl_xor_sync(0xffffffffu, s0, 2);
            s1 += __shfl_xor_sync(0xffffffffu, s1, 1);
            s1 += __shfl_xor_sync(0xffffffffu, s1, 2);
            if (fc == 0) {
                sb[wn * 128 + r0] = s0;
                sb[wn * 128 + r1] = s1;
            }
        }
        __syncthreads();

        // ---- per-row running state update ----
        if (tid < 128) {
            const float mo = rm[tid];
            float tm = fmaxf(fmaxf(red[tid], red[128 + tid]),
                             fmaxf(red[256 + tid], red[384 + tid]));
            const float mn = fmaxf(mo, tm);
            const float al = fast_exp2(mo - mn);
            const float ts = sb[tid] + sb[128 + tid] + sb[256 + tid] + sb[384 + tid];
            rl[tid] = rl[tid] * al + ts;
            rm[tid] = mn;
            ab[tid] = al;
        }
        __syncthreads();

        // ---- PV: acc_o = acc_o*alpha + P @ V ----
        {
            const int r0 = warp * 16 + fr;
            const float al0 = ab[r0], al1 = ab[r0 + 8];
            #pragma unroll
            for (int nt = 0; nt < 8; nt++) {
                acc_o[nt][0] *= al0; acc_o[nt][1] *= al0;
                acc_o[nt][2] *= al1; acc_o[nt][3] *= al1;
            }
            #pragma unroll
            for (int ks = 0; ks < 8; ks++) {
                uint32_t a[4];
                const int base = r0 * FP_STR + ks * 8 + fc;
                a[0] = Ps[base];
                a[1] = Ps[base + 8 * FP_STR];
                a[2] = Ps[base + 4];
                a[3] = Ps[base + 8 * FP_STR + 4];
                const int k0r = ks * 16 + 2 * fc;
                #pragma unroll
                for (int nt = 0; nt < 8; nt++) {
                    const unsigned short* vp = &Vs[nt * 8 + fr];
                    uint32_t bfr[2];
                    bfr[0] = (uint32_t)vp[k0r * FV_STR] |
                             ((uint32_t)vp[(k0r + 1) * FV_STR] << 16);
                    bfr[1] = (uint32_t)vp[(k0r + 8) * FV_STR] |
                             ((uint32_t)vp[(k0r + 9) * FV_STR] << 16);
                    mma16(acc_o[nt], a, bfr);
                }
            }
        }
    }

    // ---- normalize and write (bf16) ----
    {
        const int r0 = warp * 16 + fr;
        const float i0 = 1.0f / rl[r0];
        const float i1 = 1.0f / rl[r0 + 8];
        #pragma unroll
        for (int nt = 0; nt < 8; nt++) {
            const int c = nt * 8 + 2 * fc;
            *(uint32_t*)&Aout[(tb + q0 + r0) * HIDN + h * 64 + c] =
                bf2(acc_o[nt][0] * i0, acc_o[nt][1] * i0);
            *(uint32_t*)&Aout[(tb + q0 + r0 + 8) * HIDN + h * 64 + c] =
                bf2(acc_o[nt][2] * i1, acc_o[nt][3] * i1);
        }
    }
}

// ---------------------------------------------------------------------------
// launch
// ---------------------------------------------------------------------------
extern "C" void kernel_launch(void* const* d_in, const int* in_sizes, int n_in,
                              void* d_out, int out_size)
{
    (void)in_sizes; (void)n_in; (void)out_size;
    const float* x    = (const float*)d_in[0];
    const float* mask = (const float*)d_in[1];
    const float* Wq   = (const float*)d_in[2];
    const float* bq   = (const float*)d_in[3];
    const float* Wk   = (const float*)d_in[4];
    const float* bk   = (const float*)d_in[5];
    const float* Wv   = (const float*)d_in[6];
    const float* bv   = (const float*)d_in[7];
    const float* Wo   = (const float*)d_in[8];
    const float* bo   = (const float*)d_in[9];
    float* out = (float*)d_out;

    __nv_bfloat16 *xb, *WqT, *WkT, *WvT, *WoT, *Qb, *Kb, *Vb, *Ab;
    cudaGetSymbolAddress((void**)&xb,  g_xb);
    cudaGetSymbolAddress((void**)&WqT, g_WqT);
    cudaGetSymbolAddress((void**)&WkT, g_WkT);
    cudaGetSymbolAddress((void**)&WvT, g_WvT);
    cudaGetSymbolAddress((void**)&WoT, g_WoT);
    cudaGetSymbolAddress((void**)&Qb,  g_Qb);
    cudaGetSymbolAddress((void**)&Kb,  g_Kb);
    cudaGetSymbolAddress((void**)&Vb,  g_Vb);
    cudaGetSymbolAddress((void**)&Ab,  g_Ab);

    cudaFuncSetAttribute(fa_kernel, cudaFuncAttributeMaxDynamicSharedMemorySize, FA_SMEM);
    cudaFuncSetAttribute(qkv_gemm_kernel, cudaFuncAttributeMaxDynamicSharedMemorySize, G_SMEM);
    cudaFuncSetAttribute(o_gemm_kernel, cudaFuncAttributeMaxDynamicSharedMemorySize, G_SMEM);

    // prep: bf16 conversions + weight transposes
    cvt_x_kernel<<<2048, 256>>>(x, xb);
    transpose_w_kernel<<<dim3(32, 32), 256>>>(Wq, WqT, HIDN, HIDN);
    transpose_w_kernel<<<dim3(8, 32), 256>>>(Wk, WkT, HIDN, KVN);
    transpose_w_kernel<<<dim3(8, 32), 256>>>(Wv, WvT, HIDN, KVN);
    transpose_w_kernel<<<dim3(32, 32), 256>>>(Wo, WoT, HIDN, HIDN);

    // fused Q/K/V projections (bf16 NT)
    qkv_gemm_kernel<<<dim3(24, 16), 256, G_SMEM>>>(xb, WqT, bq, Qb,
                                                   WkT, bk, Kb, WvT, bv, Vb);
    // fused attention
    fa_kernel<<<dim3(8, 64), 256, FA_SMEM>>>(Qb, Kb, Vb, mask, Ab);
    // output projection + bias + residual
    o_gemm_kernel<<<dim3(16, 16), 256, G_SMEM>>>(Ab, WoT, bo, out, x);
}